// round 8
// baseline (speedup 1.0000x reference)
#include <cuda_runtime.h>
#include <cstdint>

// ---------------- configuration ----------------
#define T_STEPS   30
#define HDIM      128
#define EDIM      16
#define KDIM      144          // 128 (h) + 16 (x)
#define BTILE     64           // batch elements per CTA
#define TM        8            // batch per thread
#define TU        2            // units per thread
#define NTHREADS  512
#define KC        36           // k per staged chunk
#define NCHUNK    4            // 4*36 = 144
#define HP        68           // h_sh row pitch: 272B (16B-aligned); HP ≡ 4 (mod 32 banks) -> conflict-free STS.128 at stride HP
#define WCHUNK_FLOATS (KC*512) // 18432 floats = 72KB per chunk

// plane-separated permuted weights:
//   g_Wp[((k*2 + p)*64 + ug)*4 + g]  = W[row = g*128 + (ug + 64*p)][k]
// lane (=ug) stride within a plane is 16B -> conflict-free LDS.128
__device__ float g_Wp[KDIM * 512];
__device__ float g_biasp[512];     // b_ih + b_hh, same (p,ug,g) plane layout

typedef unsigned long long u64;

__device__ __forceinline__ u64 fma2(u64 a, u64 b, u64 c) {
    u64 d;
    asm("fma.rn.f32x2 %0, %1, %2, %3;" : "=l"(d) : "l"(a), "l"(b), "l"(c));
    return d;
}
__device__ __forceinline__ u64 dup2(float x) {
    u64 d;
    asm("mov.b64 %0, {%1, %2};" : "=l"(d) : "f"(x), "f"(x));
    return d;
}
__device__ __forceinline__ void unpk(u64 v, float& lo, float& hi) {
    asm("mov.b64 {%0, %1}, %2;" : "=f"(lo), "=f"(hi) : "l"(v));
}
__device__ __forceinline__ float sigmoidf_(float x) {
    float e = __expf(-x);                  // overflow-safe: x<<0 -> e=inf -> 0
    return __fdividef(1.0f, 1.0f + e);
}
__device__ __forceinline__ float tanhf_(float x) {
    float a = fabsf(x);
    float e = __expf(-2.0f * a);           // in (0,1], no overflow
    float r = __fdividef(1.0f - e, 1.0f + e);
    return copysignf(r, x);
}
__device__ __forceinline__ void cp16(uint32_t dst, const void* src) {
    asm volatile("cp.async.cg.shared.global [%0], [%1], 16;" :: "r"(dst), "l"(src) : "memory");
}
__device__ __forceinline__ void cp_commit() { asm volatile("cp.async.commit_group;" ::: "memory"); }
__device__ __forceinline__ void cp_wait0()  { asm volatile("cp.async.wait_group 0;" ::: "memory"); }

// ---------------- weight permutation pre-pass ----------------
__global__ void prep_kernel(const float* __restrict__ W_ih, const float* __restrict__ b_ih,
                            const float* __restrict__ W_hh, const float* __restrict__ b_hh) {
    int idx = blockIdx.x * blockDim.x + threadIdx.x;
    if (idx >= KDIM * 512) return;
    int k   = idx >> 9;
    int rem = idx & 511;
    int g   = rem & 3;            // gate i,f,g,o (PyTorch order)
    int f4  = rem >> 2;           // 0..127
    int p   = f4 >> 6;            // plane
    int ug  = f4 & 63;
    int u   = ug + 64 * p;        // unit ownership: thread ug owns u=ug (plane0), u=ug+64 (plane1)
    int row = g * HDIM + u;
    g_Wp[idx] = (k < HDIM) ? W_hh[row * HDIM + k] : W_ih[row * EDIM + (k - HDIM)];
    if (idx < 512) g_biasp[idx] = b_ih[row] + b_hh[row];
}

// ---------------- main persistent LSTM kernel ----------------
__device__ __forceinline__ void stage_chunk(int chunk, float* dstbuf, int tid) {
    const float4* src = (const float4*)(g_Wp + (size_t)chunk * WCHUNK_FLOATS);
    uint32_t dbase = (uint32_t)__cvta_generic_to_shared(dstbuf);
#pragma unroll
    for (int r = 0; r < 9; r++) {
        int i = tid + r * NTHREADS;   // covers 4608 float4 = 18432 floats
        cp16(dbase + i * 16, src + i);
    }
}

__global__ __launch_bounds__(NTHREADS, 1)
void lstm_kernel(const float* __restrict__ rel_in,   // last_obs_rel (B,2)
                 const float* __restrict__ h0,       // (1,B,128)
                 const float* __restrict__ c0,       // (1,B,128)
                 const float* __restrict__ W_sp,     // (16,2)
                 const float* __restrict__ b_sp,     // (16)
                 const float* __restrict__ W_out,    // (2,128)
                 const float* __restrict__ b_out,    // (2)
                 float* __restrict__ out)            // (B,30,2)
{
    extern __shared__ float smem[];
    float* wbuf0   = smem;
    float* wbuf1   = smem + WCHUNK_FLOATS;
    float* h_sh    = smem + 2 * WCHUNK_FLOATS;        // [144][HP]
    float* wout_sh = h_sh + KDIM * HP;                // 256
    float* wsp_sh  = wout_sh + 256;                   // 32
    float* bsp_sh  = wsp_sh + 32;                     // 16
    float* bout_sh = bsp_sh + 16;                     // 8 (2 used)
    float* rel_sh  = bout_sh + 8;                     // 128
    float* bias_sh = rel_sh + 128;                    // 512 (plane layout)

    const int tid    = threadIdx.x;
    const int ug     = tid & 63;          // owns units ug and ug+64
    const int mg     = tid >> 6;          // batch group
    const int m0     = mg * TM;
    const int batch0 = blockIdx.x * BTILE;

    // small weights -> shared
    if (tid < 256) wout_sh[tid] = W_out[tid];
    if (tid < 32)  wsp_sh[tid]  = W_sp[tid];
    if (tid < 16)  bsp_sh[tid]  = b_sp[tid];
    if (tid < 2)   bout_sh[tid] = b_out[tid];
    bias_sh[tid] = g_biasp[tid];

    // h0 -> h_sh transposed: h_sh[u][m]
    {
        const float4* h4 = (const float4*)h0;
#pragma unroll
        for (int r = 0; r < 4; r++) {
            int i = tid + r * NTHREADS;            // 0..2047
            int m = i >> 5;
            int q = i & 31;
            float4 v = h4[(size_t)(batch0 + m) * 32 + q];
            h_sh[(4 * q + 0) * HP + m] = v.x;
            h_sh[(4 * q + 1) * HP + m] = v.y;
            h_sh[(4 * q + 2) * HP + m] = v.z;
            h_sh[(4 * q + 3) * HP + m] = v.w;
        }
    }
    __syncthreads();   // wsp/bsp visible before x0

    // x0 = tanh(last_obs_rel @ W_sp^T + b_sp) -> h_sh rows 128..143
#pragma unroll
    for (int r = 0; r < 2; r++) {
        int idx = tid + r * NTHREADS;              // 0..1023
        int m = idx >> 4;
        int e = idx & 15;
        float r0 = rel_in[(size_t)(batch0 + m) * 2 + 0];
        float r1 = rel_in[(size_t)(batch0 + m) * 2 + 1];
        float xv = tanhf_(fmaf(wsp_sh[e * 2 + 0], r0, fmaf(wsp_sh[e * 2 + 1], r1, bsp_sh[e])));
        h_sh[(HDIM + e) * HP + m] = xv;
    }

    // c0 -> registers (per-thread (m, u) ownership; u = ug + 64*ul)
    float creg[TM][TU];
#pragma unroll
    for (int mi = 0; mi < TM; mi++)
#pragma unroll
        for (int ul = 0; ul < TU; ul++)
            creg[mi][ul] = c0[(size_t)(batch0 + m0 + mi) * HDIM + (ug + 64 * ul)];

    // prefetch first weight chunk
    stage_chunk(0, wbuf0, tid);
    cp_commit();

    int cc = 0;  // global chunk counter
    for (int t = 0; t < T_STEPS; t++) {
        // init accumulators with fused bias (both batch lanes same bias)
        u64 acc[4][8];
        {
            float4 b0 = *(const float4*)&bias_sh[ug * 4];          // plane 0 (u=ug)
            float4 b1 = *(const float4*)&bias_sh[256 + ug * 4];    // plane 1 (u=ug+64)
            u64 bj0 = dup2(b0.x), bj1 = dup2(b0.y), bj2 = dup2(b0.z), bj3 = dup2(b0.w);
            u64 bj4 = dup2(b1.x), bj5 = dup2(b1.y), bj6 = dup2(b1.z), bj7 = dup2(b1.w);
#pragma unroll
            for (int m2 = 0; m2 < 4; m2++) {
                acc[m2][0] = bj0; acc[m2][1] = bj1; acc[m2][2] = bj2; acc[m2][3] = bj3;
                acc[m2][4] = bj4; acc[m2][5] = bj5; acc[m2][6] = bj6; acc[m2][7] = bj7;
            }
        }

#pragma unroll 1
        for (int c = 0; c < NCHUNK; c++) {
            cp_wait0();          // chunk cc staged
            __syncthreads();     // all warps past previous chunk compute; staged data visible
            {                    // prefetch next chunk into the other buffer
                int nc = cc + 1;
                stage_chunk(nc & 3, (nc & 1) ? wbuf1 : wbuf0, tid);
                cp_commit();
            }
            const float* wb = (cc & 1) ? wbuf1 : wbuf0;
            const int kb = (cc & 3) * KC;

#pragma unroll 2
            for (int kk = 0; kk < KC; kk++) {
                const float* hrow = &h_sh[(kb + kk) * HP + m0];
                ulonglong2 hA = *(const ulonglong2*)(hrow);       // pairs (m0,m0+1),(m0+2,m0+3)
                ulonglong2 hB = *(const ulonglong2*)(hrow + 4);
                // plane-separated, conflict-free weight loads (16B lane stride)
                const float4* wpA = (const float4*)wb + (kk * 128 + ug);
                float4 w0 = wpA[0];        // plane 0: gates i,f,g,o of u=ug
                float4 w1 = wpA[64];       // plane 1: gates i,f,g,o of u=ug+64
                u64 d0 = dup2(w0.x), d1 = dup2(w0.y), d2 = dup2(w0.z), d3 = dup2(w0.w);
                u64 d4 = dup2(w1.x), d5 = dup2(w1.y), d6 = dup2(w1.z), d7 = dup2(w1.w);
                u64 hp0 = hA.x, hp1 = hA.y, hp2 = hB.x, hp3 = hB.y;
#define FMAROW(M2, HP_) \
                acc[M2][0] = fma2(HP_, d0, acc[M2][0]); acc[M2][1] = fma2(HP_, d1, acc[M2][1]); \
                acc[M2][2] = fma2(HP_, d2, acc[M2][2]); acc[M2][3] = fma2(HP_, d3, acc[M2][3]); \
                acc[M2][4] = fma2(HP_, d4, acc[M2][4]); acc[M2][5] = fma2(HP_, d5, acc[M2][5]); \
                acc[M2][6] = fma2(HP_, d6, acc[M2][6]); acc[M2][7] = fma2(HP_, d7, acc[M2][7]);
                FMAROW(0, hp0)
                FMAROW(1, hp1)
                FMAROW(2, hp2)
                FMAROW(3, hp3)
#undef FMAROW
            }
            cc++;
        }

        __syncthreads();   // all GEMM reads of h_sh done before overwrite

        // activations + state update; write h_new transposed to h_sh
#pragma unroll
        for (int ul = 0; ul < TU; ul++) {
            float hn[TM];
#pragma unroll
            for (int m2 = 0; m2 < 4; m2++) {
                float zi0, zi1, zf0, zf1, zg0, zg1, zo0, zo1;
                unpk(acc[m2][ul * 4 + 0], zi0, zi1);
                unpk(acc[m2][ul * 4 + 1], zf0, zf1);
                unpk(acc[m2][ul * 4 + 2], zg0, zg1);
                unpk(acc[m2][ul * 4 + 3], zo0, zo1);
                {
                    float i_ = sigmoidf_(zi0), f_ = sigmoidf_(zf0);
                    float g_ = tanhf_(zg0),    o_ = sigmoidf_(zo0);
                    float cn = f_ * creg[2 * m2 + 0][ul] + i_ * g_;
                    creg[2 * m2 + 0][ul] = cn;
                    hn[2 * m2 + 0] = o_ * tanhf_(cn);
                }
                {
                    float i_ = sigmoidf_(zi1), f_ = sigmoidf_(zf1);
                    float g_ = tanhf_(zg1),    o_ = sigmoidf_(zo1);
                    float cn = f_ * creg[2 * m2 + 1][ul] + i_ * g_;
                    creg[2 * m2 + 1][ul] = cn;
                    hn[2 * m2 + 1] = o_ * tanhf_(cn);
                }
            }
            int u = ug + 64 * ul;      // per-lane store stride = HP floats ≡ 4 banks -> conflict-free
            *(float4*)&h_sh[u * HP + m0]     = make_float4(hn[0], hn[1], hn[2], hn[3]);
            *(float4*)&h_sh[u * HP + m0 + 4] = make_float4(hn[4], hn[5], hn[6], hn[7]);
        }
        __syncthreads();

        // rel_pos = h_new @ W_out^T + b_out  (128 threads: 64 m x 2 comps)
        if (tid < 128) {
            int comp = tid >> 6;
            int m    = tid & 63;
            const float* wo = &wout_sh[comp * HDIM];
            float s0 = 0.f, s1 = 0.f, s2 = 0.f, s3 = 0.f;
#pragma unroll
            for (int u = 0; u < HDIM; u += 4) {
                s0 = fmaf(h_sh[(u + 0) * HP + m], wo[u + 0], s0);
                s1 = fmaf(h_sh[(u + 1) * HP + m], wo[u + 1], s1);
                s2 = fmaf(h_sh[(u + 2) * HP + m], wo[u + 2], s2);
                s3 = fmaf(h_sh[(u + 3) * HP + m], wo[u + 3], s3);
            }
            float r = (s0 + s1) + (s2 + s3) + bout_sh[comp];
            rel_sh[m * 2 + comp] = r;
            out[(size_t)(batch0 + m) * (T_STEPS * 2) + t * 2 + comp] = r;
        }
        __syncthreads();

        // x_{t+1} = tanh(rel_pos @ W_sp^T + b_sp) -> h_sh rows 128..143
#pragma unroll
        for (int r2 = 0; r2 < 2; r2++) {
            int idx = tid + r2 * NTHREADS;
            int m = idx >> 4;
            int e = idx & 15;
            float xv = tanhf_(fmaf(wsp_sh[e * 2 + 0], rel_sh[m * 2 + 0],
                              fmaf(wsp_sh[e * 2 + 1], rel_sh[m * 2 + 1], bsp_sh[e])));
            h_sh[(HDIM + e) * HP + m] = xv;
        }
        // next chunk-top __syncthreads makes these visible before the GEMM reads
    }
}

// ---------------- launch ----------------
extern "C" void kernel_launch(void* const* d_in, const int* in_sizes, int n_in,
                              void* d_out, int out_size) {
    const float* last_obs_rel = (const float*)d_in[1];
    const float* h0    = (const float*)d_in[2];
    const float* c0    = (const float*)d_in[3];
    const float* W_sp  = (const float*)d_in[4];
    const float* b_sp  = (const float*)d_in[5];
    const float* W_ih  = (const float*)d_in[6];
    const float* b_ih  = (const float*)d_in[7];
    const float* W_hh  = (const float*)d_in[8];
    const float* b_hh  = (const float*)d_in[9];
    const float* W_out = (const float*)d_in[10];
    const float* b_out = (const float*)d_in[11];
    float* out = (float*)d_out;

    const int batch = in_sizes[2] / HDIM;          // h0 is (1, B, 128)
    const int nblocks = batch / BTILE;

    // shared: 2 W chunks + h_sh + misc
    const int smem_floats = 2 * WCHUNK_FLOATS + KDIM * HP + 256 + 32 + 16 + 8 + 128 + 512;
    const int smem_bytes = smem_floats * (int)sizeof(float);   // ~190KB
    cudaFuncSetAttribute(lstm_kernel, cudaFuncAttributeMaxDynamicSharedMemorySize, smem_bytes);

    prep_kernel<<<(KDIM * 512 + 511) / 512, 512>>>(W_ih, b_ih, W_hh, b_hh);
    lstm_kernel<<<nblocks, NTHREADS, smem_bytes>>>(last_obs_rel, h0, c0,
                                                   W_sp, b_sp, W_out, b_out, out);
}

// round 10
// speedup vs baseline: 2.3059x; 2.3059x over previous
#include <cuda_runtime.h>
#include <cuda_fp16.h>
#include <cstdint>

#define T_STEPS 30
#define NT 512
#define PITCH 336                 // A row pitch bytes (84 words = 20 mod 32: ldmatrix conflict-free)
#define NCHUNKS (T_STEPS * 9)     // 270

// smem byte offsets
#define A_OFF    0                // 64 x 336 = 21504
#define RING_OFF 21504            // 4 x 32768
#define BIAS_OFF 152576           // 512 f32
#define WOUT_OFF 154624           // 256 f32
#define WSP_OFF  155648           // 32 f32
#define BSP_OFF  155776           // 16 f32
#define BOUT_OFF 155840           // 2 f32 (pad 16)
#define RELP_OFF 155856           // 4*64*2 f32
#define RELS_OFF 157904           // 128*2 f32
#define SMEM_REQ (158928 + 128)

// B image: 9 chunks x [p(2)][ntg(64)][lane(32)][q(2)] u32 (fragment-packed, hi/lo planes)
__device__ uint32_t g_B[9 * 8192];
__device__ float    g_bias[512];   // indexed by n = 4u+g

__device__ __forceinline__ uint32_t smem_u32(const void* p) {
    uint32_t a;
    asm("{ .reg .u64 t; cvta.to.shared.u64 t, %1; cvt.u32.u64 %0, t; }" : "=r"(a) : "l"(p));
    return a;
}
__device__ __forceinline__ void mma16816(float* d, const uint32_t* a, uint32_t b0, uint32_t b1) {
    asm volatile("mma.sync.aligned.m16n8k16.row.col.f32.f16.f16.f32 "
                 "{%0,%1,%2,%3}, {%4,%5,%6,%7}, {%8,%9}, {%0,%1,%2,%3};"
                 : "+f"(d[0]), "+f"(d[1]), "+f"(d[2]), "+f"(d[3])
                 : "r"(a[0]), "r"(a[1]), "r"(a[2]), "r"(a[3]), "r"(b0), "r"(b1));
}
__device__ __forceinline__ void ldmatrix4(uint32_t* a, uint32_t addr) {
    asm volatile("ldmatrix.sync.aligned.m8n8.x4.shared.b16 {%0,%1,%2,%3}, [%4];"
                 : "=r"(a[0]), "=r"(a[1]), "=r"(a[2]), "=r"(a[3]) : "r"(addr));
}
__device__ __forceinline__ void lds_v2(uint32_t& x, uint32_t& y, uint32_t addr) {
    asm volatile("ld.shared.v2.u32 {%0,%1}, [%2];" : "=r"(x), "=r"(y) : "r"(addr));
}
__device__ __forceinline__ void cp16(uint32_t dst, const void* src) {
    asm volatile("cp.async.cg.shared.global [%0], [%1], 16;" :: "r"(dst), "l"(src) : "memory");
}
__device__ __forceinline__ void cp_commit() { asm volatile("cp.async.commit_group;" ::: "memory"); }
__device__ __forceinline__ float sigmoidf_(float x) {
    float e = __expf(-x);
    return __fdividef(1.0f, 1.0f + e);
}
__device__ __forceinline__ float tanhf_(float x) {
    float a = fabsf(x);
    float e = __expf(-2.0f * a);
    float r = __fdividef(1.0f - e, 1.0f + e);
    return copysignf(r, x);
}
// k-permutation: u_in -> k'  (makes each thread's owned units contiguous in k)
__device__ __forceinline__ int sig_k(int u) {
    return 32 * (u >> 5) + 16 * (u & 1) + ((u & 31) >> 1);
}

// ---------------- prep: fragment-packed hi/lo fp16 B image + bias ----------------
__global__ void prep_kernel(const float* __restrict__ Wih, const float* __restrict__ bih,
                            const float* __restrict__ Whh, const float* __restrict__ bhh) {
    int idx = blockIdx.x * blockDim.x + threadIdx.x;
    if (idx < 73728) {
        int kt = idx / 8192, rem = idx - kt * 8192;
        int p = rem >> 12, rem2 = rem & 4095;
        int ntg = rem2 >> 6, r3 = rem2 & 63;
        int l = r3 >> 1, q = r3 & 1;
        int n = 8 * ntg + (l >> 2), c = l & 3;
        int row = (n & 3) * 128 + (n >> 2);     // torch weight row for gate (n&3), unit (n>>2)
        uint32_t pk = 0;
#pragma unroll
        for (int h2 = 0; h2 < 2; h2++) {
            int k = 16 * kt + 2 * c + 8 * q + h2;
            float wv;
            if (k < 128) {
                int nc2 = k >> 5, rm = k & 31, d2 = rm >> 4, j2 = rm & 15;
                wv = Whh[row * 128 + (32 * nc2 + 2 * j2 + d2)];   // inverse of sig_k
            } else {
                wv = Wih[row * 16 + (k - 128)];
            }
            __half hi = __float2half_rn(wv);
            __half v = p ? __float2half_rn(wv - __half2float(hi)) : hi;
            pk |= (uint32_t)__half_as_ushort(v) << (16 * h2);
        }
        g_B[idx] = pk;
    } else if (idx < 74240) {
        int n = idx - 73728;
        int row = (n & 3) * 128 + (n >> 2);
        g_bias[n] = bih[row] + bhh[row];
    }
}

// ---------------- main kernel ----------------
__global__ __launch_bounds__(NT, 1)
void lstm_mma(const float* __restrict__ rel_in, const float* __restrict__ h0,
              const float* __restrict__ c0, const float* __restrict__ W_sp,
              const float* __restrict__ b_sp, const float* __restrict__ W_out,
              const float* __restrict__ b_out, float* __restrict__ out) {
    extern __shared__ char sm_[];
    char* base = (char*)(((uintptr_t)sm_ + 127) & ~(uintptr_t)127);
    const uint32_t sb = smem_u32(base);
    const int tid = threadIdx.x, w = tid >> 5, l = tid & 31;
    const int mr = w >> 2, nc = w & 3;        // warp: m-rows [16mr,16mr+16), n-cols [128nc,..)
    const int c = l & 3, quad = l >> 2;
    const int dlt = c >> 1;                   // unit parity this lane owns post-exchange
    const int row_loc = quad + 8 * (c & 1);   // post-exchange local row within warp m-tile
    const int m_loc = 16 * mr + row_loc;      // CTA-local batch row (post-exchange)
    const int b0 = blockIdx.x * 64;

    float* bias_f = (float*)(base + BIAS_OFF);
    float* wout_f = (float*)(base + WOUT_OFF);
    float* wsp_f  = (float*)(base + WSP_OFF);
    float* bsp_f  = (float*)(base + BSP_OFF);
    float* bout_f = (float*)(base + BOUT_OFF);
    float* relp_f = (float*)(base + RELP_OFF);
    float* rels_f = (float*)(base + RELS_OFF);

    // small weights
    if (tid < 512) bias_f[tid] = g_bias[tid];
    if (tid < 256) wout_f[tid] = W_out[tid];
    if (tid < 32)  wsp_f[tid]  = W_sp[tid];
    if (tid < 16)  bsp_f[tid]  = b_sp[tid];
    if (tid < 2)   bout_f[tid] = b_out[tid];

    // A init: h0 -> fp16 at permuted k'
    for (int i = tid; i < 8192; i += NT) {
        int m = i >> 7, u = i & 127;
        unsigned short hv = __half_as_ushort(__float2half_rn(h0[(size_t)(b0 + m) * 128 + u]));
        asm volatile("st.shared.u16 [%0], %1;" :: "r"(sb + A_OFF + m * PITCH + sig_k(u) * 2), "h"(hv));
    }
    // x0
    for (int i = tid; i < 1024; i += NT) {
        int m = i >> 4, e = i & 15;
        float r0 = rel_in[(size_t)(b0 + m) * 2], r1 = rel_in[(size_t)(b0 + m) * 2 + 1];
        float xv = tanhf_(fmaf(W_sp[2 * e], r0, fmaf(W_sp[2 * e + 1], r1, b_sp[e])));
        unsigned short hv = __half_as_ushort(__float2half_rn(xv));
        asm volatile("st.shared.u16 [%0], %1;" :: "r"(sb + A_OFF + m * PITCH + (128 + e) * 2), "h"(hv));
    }
    // c state (post-exchange ownership: row m_loc, units u = 2*(16nc+j)+dlt)
    float cst[16];
#pragma unroll
    for (int j = 0; j < 16; j++)
        cst[j] = c0[(size_t)(b0 + m_loc) * 128 + (2 * (16 * nc + j) + dlt)];

    // stage chunks 0..2
    for (int g = 0; g < 3; g++) {
        const char* src = (const char*)(g_B + g * 8192);
#pragma unroll
        for (int i = 0; i < 4; i++)
            cp16(sb + RING_OFF + g * 32768 + (tid + i * NT) * 16, src + (tid + i * NT) * 16);
        cp_commit();
    }
    __syncthreads();

    int qc = 3;
    const uint32_t aAddrBase = sb + A_OFF + (16 * mr + (l & 15)) * PITCH + (l >> 4) * 16;
    const int uO = 2 * (16 * nc) + dlt;       // first owned unit (j=0)

    for (int t = 0; t < T_STEPS; t++) {
        float acc[16][4];
#pragma unroll
        for (int j = 0; j < 16; j++) {
            float2 bv = *(const float2*)(bias_f + (8 * (nc * 16 + j) + 2 * c));
            acc[j][0] = bv.x; acc[j][1] = bv.y; acc[j][2] = bv.x; acc[j][3] = bv.y;
        }
#pragma unroll 1
        for (int kt = 0; kt < 9; kt++) {
            int G = t * 9 + kt;
            asm volatile("cp.async.wait_group 2;" ::: "memory");
            __syncthreads();
            if (qc < NCHUNKS) {
                const char* src = (const char*)(g_B + (qc % 9) * 8192);
                uint32_t dst = sb + RING_OFF + (qc & 3) * 32768;
#pragma unroll
                for (int i = 0; i < 4; i++)
                    cp16(dst + (tid + i * NT) * 16, src + (tid + i * NT) * 16);
                cp_commit();
                qc++;
            }
            uint32_t a[4];
            ldmatrix4(a, aAddrBase + kt * 32);
            uint32_t slot = sb + RING_OFF + (G & 3) * 32768;
            uint32_t baddr = slot + ((nc * 16) * 32 + l) * 8;
#pragma unroll
            for (int j = 0; j < 16; j++) {
                uint32_t bh0, bh1, bl0, bl1;
                lds_v2(bh0, bh1, baddr);            // hi plane
                lds_v2(bl0, bl1, baddr + 16384);    // lo plane
                mma16816(acc[j], a, bh0, bh1);
                mma16816(acc[j], a, bl0, bl1);
                baddr += 256;
            }
        }
        __syncthreads();   // all warps done reading A before h overwrite

        // ---- epilogue ----
        float px = 0.f, py = 0.f;
        uint32_t hpk[8];
#pragma unroll
        for (int j = 0; j < 16; j++) {
            float s0 = (c & 1) ? acc[j][0] : acc[j][2];
            float s1 = (c & 1) ? acc[j][1] : acc[j][3];
            float r0 = __shfl_xor_sync(0xffffffffu, s0, 1);
            float r1 = __shfl_xor_sync(0xffffffffu, s1, 1);
            float zi, zf, zg, zo;
            if ((c & 1) == 0) { zi = acc[j][0]; zf = acc[j][1]; zg = r0; zo = r1; }
            else              { zi = r0;        zf = r1;        zg = acc[j][2]; zo = acc[j][3]; }
            float cn = sigmoidf_(zf) * cst[j] + sigmoidf_(zi) * tanhf_(zg);
            cst[j] = cn;
            float hv = sigmoidf_(zo) * tanhf_(cn);
            int u = uO + 2 * j;
            px = fmaf(hv, wout_f[u], px);
            py = fmaf(hv, wout_f[128 + u], py);
            uint32_t hb = (uint32_t)__half_as_ushort(__float2half_rn(hv));
            if (j & 1) hpk[j >> 1] |= hb << 16; else hpk[j >> 1] = hb;
        }
        {   // h write-back: k' = 32nc + 16*dlt + j contiguous
            uint32_t ha = sb + A_OFF + m_loc * PITCH + (32 * nc + 16 * dlt) * 2;
            asm volatile("st.shared.v4.u32 [%0], {%1,%2,%3,%4};"
                         :: "r"(ha), "r"(hpk[0]), "r"(hpk[1]), "r"(hpk[2]), "r"(hpk[3]));
            asm volatile("st.shared.v4.u32 [%0], {%1,%2,%3,%4};"
                         :: "r"(ha + 16), "r"(hpk[4]), "r"(hpk[5]), "r"(hpk[6]), "r"(hpk[7]));
        }
        px += __shfl_xor_sync(0xffffffffu, px, 2);
        py += __shfl_xor_sync(0xffffffffu, py, 2);
        if (c < 2)
            *(float2*)(relp_f + (nc * 64 + m_loc) * 2) = make_float2(px, py);
        __syncthreads();
        if (tid < 128) {
            int m = tid >> 1, cp = tid & 1;
            float r = relp_f[(0 * 64 + m) * 2 + cp] + relp_f[(1 * 64 + m) * 2 + cp] +
                      relp_f[(2 * 64 + m) * 2 + cp] + relp_f[(3 * 64 + m) * 2 + cp] + bout_f[cp];
            rels_f[m * 2 + cp] = r;
            out[(size_t)(b0 + m) * (T_STEPS * 2) + t * 2 + cp] = r;
        }
        __syncthreads();
        for (int i = tid; i < 1024; i += NT) {
            int m = i >> 4, e = i & 15;
            float xv = tanhf_(fmaf(wsp_f[2 * e], rels_f[m * 2],
                              fmaf(wsp_f[2 * e + 1], rels_f[m * 2 + 1], bsp_f[e])));
            unsigned short hv = __half_as_ushort(__float2half_rn(xv));
            asm volatile("st.shared.u16 [%0], %1;" :: "r"(sb + A_OFF + m * PITCH + (128 + e) * 2), "h"(hv));
        }
        // next iteration's kt=0 syncthreads orders these writes before A reads
    }
}

// ---------------- launch ----------------
extern "C" void kernel_launch(void* const* d_in, const int* in_sizes, int n_in,
                              void* d_out, int out_size) {
    const float* last_obs_rel = (const float*)d_in[1];
    const float* h0    = (const float*)d_in[2];
    const float* c0    = (const float*)d_in[3];
    const float* W_sp  = (const float*)d_in[4];
    const float* b_sp  = (const float*)d_in[5];
    const float* W_ih  = (const float*)d_in[6];
    const float* b_ih  = (const float*)d_in[7];
    const float* W_hh  = (const float*)d_in[8];
    const float* b_hh  = (const float*)d_in[9];
    const float* W_out = (const float*)d_in[10];
    const float* b_out = (const float*)d_in[11];
    float* out = (float*)d_out;

    const int batch = in_sizes[2] / 128;
    const int nblocks = batch / 64;

    cudaFuncSetAttribute(lstm_mma, cudaFuncAttributeMaxDynamicSharedMemorySize, SMEM_REQ);
    prep_kernel<<<146, 512>>>(W_ih, b_ih, W_hh, b_hh);
    lstm_mma<<<nblocks, NT, SMEM_REQ>>>(last_obs_rel, h0, c0, W_sp, b_sp, W_out, b_out, out);
}

// round 11
// speedup vs baseline: 2.3151x; 1.0040x over previous
#include <cuda_runtime.h>
#include <cuda_fp16.h>
#include <cstdint>

#define T_STEPS 30
#define NT 512
#define PITCH 336                 // A row pitch bytes (ldmatrix conflict-free)
#define NCHUNKS (T_STEPS * 9)

// smem byte offsets
#define A_OFF    0                // 64 x 336 = 21504
#define RING_OFF 21504            // 4 x 32768
#define BIAS_OFF 152576           // 512 f32
#define WOUT_OFF 154624           // 256 f32
#define WSP_OFF  155648           // 32 f32
#define BSP_OFF  155776           // 16 f32
#define BOUT_OFF 155840           // 2 f32 (pad 16)
#define RELP_OFF 155856           // 8*64*2 f32 = 4096
#define RELS_OFF 159952           // 128*2 f32
#define SMEM_REQ (160976 + 128)

// B image: 9 chunks x [ntg(64)][lane(32)][bh0,bh1,bl0,bl1] (hi/lo packed adjacent)
__device__ uint32_t g_B[9 * 8192];
__device__ float    g_bias[512];   // indexed by n = 4u+g

__device__ __forceinline__ uint32_t smem_u32(const void* p) {
    uint32_t a;
    asm("{ .reg .u64 t; cvta.to.shared.u64 t, %1; cvt.u32.u64 %0, t; }" : "=r"(a) : "l"(p));
    return a;
}
__device__ __forceinline__ void mma16816(float* d, const uint32_t* a, uint32_t b0, uint32_t b1) {
    asm volatile("mma.sync.aligned.m16n8k16.row.col.f32.f16.f16.f32 "
                 "{%0,%1,%2,%3}, {%4,%5,%6,%7}, {%8,%9}, {%0,%1,%2,%3};"
                 : "+f"(d[0]), "+f"(d[1]), "+f"(d[2]), "+f"(d[3])
                 : "r"(a[0]), "r"(a[1]), "r"(a[2]), "r"(a[3]), "r"(b0), "r"(b1));
}
__device__ __forceinline__ void ldmatrix4(uint32_t* a, uint32_t addr) {
    asm volatile("ldmatrix.sync.aligned.m8n8.x4.shared.b16 {%0,%1,%2,%3}, [%4];"
                 : "=r"(a[0]), "=r"(a[1]), "=r"(a[2]), "=r"(a[3]) : "r"(addr));
}
__device__ __forceinline__ void lds_v4(uint32_t& x, uint32_t& y, uint32_t& z, uint32_t& u, uint32_t addr) {
    asm volatile("ld.shared.v4.u32 {%0,%1,%2,%3}, [%4];" : "=r"(x), "=r"(y), "=r"(z), "=r"(u) : "r"(addr));
}
__device__ __forceinline__ void cp16(uint32_t dst, const void* src) {
    asm volatile("cp.async.cg.shared.global [%0], [%1], 16;" :: "r"(dst), "l"(src) : "memory");
}
__device__ __forceinline__ void cp_commit() { asm volatile("cp.async.commit_group;" ::: "memory"); }
__device__ __forceinline__ float rcpf(float x) {
    float r;
    asm("rcp.approx.ftz.f32 %0, %1;" : "=f"(r) : "f"(x));
    return r;
}
__device__ __forceinline__ float tanhf_(float x) {   // init-path only
    float a = fabsf(x);
    float e = __expf(-2.0f * a);
    return copysignf((1.0f - e) * rcpf(1.0f + e), x);
}
// k-permutation: unit u -> k' so each thread's owned units are k'-contiguous
__device__ __forceinline__ int sig_k(int u) {
    return 16 * (u >> 4) + 8 * (u & 1) + ((u & 15) >> 1);
}

// ---------------- prep: fragment-packed hi/lo fp16 B image + bias ----------------
__global__ void prep_kernel(const float* __restrict__ Wih, const float* __restrict__ bih,
                            const float* __restrict__ Whh, const float* __restrict__ bhh) {
    int idx = blockIdx.x * blockDim.x + threadIdx.x;
    if (idx < 73728) {
        int kt = idx / 8192, rem = idx - kt * 8192;
        int ntg = rem >> 7, r2 = rem & 127;
        int l = r2 >> 2, s = r2 & 3;
        int p = s >> 1, q = s & 1;
        int n = 8 * ntg + (l >> 2), c = l & 3;
        int row = (n & 3) * 128 + (n >> 2);     // torch row for gate (n&3), unit (n>>2)
        uint32_t pk = 0;
#pragma unroll
        for (int h2 = 0; h2 < 2; h2++) {
            int k = 16 * kt + 2 * c + 8 * q + h2;
            float wv;
            if (k < 128) {
                int a2 = k >> 4, d2 = (k >> 3) & 1, b2 = k & 7;
                wv = Whh[row * 128 + (16 * a2 + 2 * b2 + d2)];   // inverse sig_k
            } else {
                wv = Wih[row * 16 + (k - 128)];
            }
            __half hi = __float2half_rn(wv);
            __half v = p ? __float2half_rn(wv - __half2float(hi)) : hi;
            pk |= (uint32_t)__half_as_ushort(v) << (16 * h2);
        }
        g_B[idx] = pk;
    } else if (idx < 74240) {
        int n = idx - 73728;
        int row = (n & 3) * 128 + (n >> 2);
        g_bias[n] = bih[row] + bhh[row];
    }
}

// ---------------- main kernel ----------------
__global__ __launch_bounds__(NT, 1)
void lstm_mma(const float* __restrict__ rel_in, const float* __restrict__ h0,
              const float* __restrict__ c0, const float* __restrict__ W_sp,
              const float* __restrict__ b_sp, const float* __restrict__ W_out,
              const float* __restrict__ b_out, float* __restrict__ out) {
    extern __shared__ char sm_[];
    char* base = (char*)(((uintptr_t)sm_ + 127) & ~(uintptr_t)127);
    const uint32_t sb = smem_u32(base);
    const int tid = threadIdx.x, w = tid >> 5, l = tid & 31;
    const int nc = w & 7, mr = w >> 3;         // warp: n-cols [64nc, 64nc+64), m-rows [32mr, 32mr+32)
    const int c = l & 3, quad = l >> 2;
    const int dlt = c >> 1;                    // unit parity owned post-exchange
    const int row_loc = quad + 8 * (c & 1);    // local row within a 16-row tile
    const int b0 = blockIdx.x * 64;

    float* bias_f = (float*)(base + BIAS_OFF);
    float* wout_f = (float*)(base + WOUT_OFF);
    float* wsp_f  = (float*)(base + WSP_OFF);
    float* bsp_f  = (float*)(base + BSP_OFF);
    float* bout_f = (float*)(base + BOUT_OFF);
    float* relp_f = (float*)(base + RELP_OFF);
    float* rels_f = (float*)(base + RELS_OFF);

    if (tid < 512) bias_f[tid] = g_bias[tid];
    if (tid < 256) wout_f[tid] = W_out[tid];
    if (tid < 32)  wsp_f[tid]  = W_sp[tid];
    if (tid < 16)  bsp_f[tid]  = b_sp[tid];
    if (tid < 2)   bout_f[tid] = b_out[tid];

    // A init: h0 -> fp16 at permuted k'
    for (int i = tid; i < 8192; i += NT) {
        int m = i >> 7, u = i & 127;
        unsigned short hv = __half_as_ushort(__float2half_rn(h0[(size_t)(b0 + m) * 128 + u]));
        asm volatile("st.shared.u16 [%0], %1;" :: "r"(sb + A_OFF + m * PITCH + sig_k(u) * 2), "h"(hv));
    }
    // x0
    for (int i = tid; i < 1024; i += NT) {
        int m = i >> 4, e = i & 15;
        float r0 = rel_in[(size_t)(b0 + m) * 2], r1 = rel_in[(size_t)(b0 + m) * 2 + 1];
        float xv = tanhf_(fmaf(W_sp[2 * e], r0, fmaf(W_sp[2 * e + 1], r1, b_sp[e])));
        unsigned short hv = __half_as_ushort(__float2half_rn(xv));
        asm volatile("st.shared.u16 [%0], %1;" :: "r"(sb + A_OFF + m * PITCH + (128 + e) * 2), "h"(hv));
    }
    // c state: thread owns rows 32mr+16s+row_loc (s=0,1), units 16nc+2j+dlt (j=0..7)
    float cst[16];
#pragma unroll
    for (int s = 0; s < 2; s++)
#pragma unroll
        for (int j = 0; j < 8; j++)
            cst[s * 8 + j] = c0[(size_t)(b0 + 32 * mr + 16 * s + row_loc) * 128 + (16 * nc + 2 * j + dlt)];

    // stage chunks 0..2
    for (int g = 0; g < 3; g++) {
        const char* src = (const char*)(g_B + g * 8192);
#pragma unroll
        for (int i = 0; i < 4; i++)
            cp16(sb + RING_OFF + g * 32768 + (tid + i * NT) * 16, src + (tid + i * NT) * 16);
        cp_commit();
    }
    __syncthreads();

    int qc = 3;
    const uint32_t aAddr0 = sb + A_OFF + (32 * mr + (l & 15)) * PITCH + (l >> 4) * 16;
    const int uO = 16 * nc + dlt;

    for (int t = 0; t < T_STEPS; t++) {
        float acc[2][8][4];
#pragma unroll
        for (int j = 0; j < 8; j++) {
            float2 bv = *(const float2*)(bias_f + (8 * (nc * 8 + j) + 2 * c));
#pragma unroll
            for (int s = 0; s < 2; s++) {
                acc[s][j][0] = bv.x; acc[s][j][1] = bv.y;
                acc[s][j][2] = bv.x; acc[s][j][3] = bv.y;
            }
        }
#pragma unroll 1
        for (int kt = 0; kt < 9; kt++) {
            int G = t * 9 + kt;
            asm volatile("cp.async.wait_group 2;" ::: "memory");
            __syncthreads();
            if (qc < NCHUNKS) {
                const char* src = (const char*)(g_B + (qc % 9) * 8192);
                uint32_t dst = sb + RING_OFF + (qc & 3) * 32768;
#pragma unroll
                for (int i = 0; i < 4; i++)
                    cp16(dst + (tid + i * NT) * 16, src + (tid + i * NT) * 16);
                cp_commit();
                qc++;
            }
            uint32_t a0[4], a1[4];
            ldmatrix4(a0, aAddr0 + kt * 32);
            ldmatrix4(a1, aAddr0 + 16 * PITCH + kt * 32);
            uint32_t slot = sb + RING_OFF + (G & 3) * 32768;
            uint32_t baddr = slot + ((nc * 8) * 32 + l) * 16;
#pragma unroll
            for (int j = 0; j < 8; j++) {
                uint32_t bh0, bh1, bl0, bl1;
                lds_v4(bh0, bh1, bl0, bl1, baddr);
                mma16816(acc[0][j], a0, bh0, bh1);
                mma16816(acc[0][j], a0, bl0, bl1);
                mma16816(acc[1][j], a1, bh0, bh1);
                mma16816(acc[1][j], a1, bl0, bl1);
                baddr += 512;
            }
        }
        __syncthreads();   // all warps done reading A before h overwrite

        // ---- epilogue ----
        float px[2] = {0.f, 0.f}, py[2] = {0.f, 0.f};
#pragma unroll
        for (int s = 0; s < 2; s++) {
            uint32_t hpk[4];
#pragma unroll
            for (int j = 0; j < 8; j++) {
                float* A4 = acc[s][j];
                float s0 = (c & 1) ? A4[0] : A4[2];
                float s1 = (c & 1) ? A4[1] : A4[3];
                float r0 = __shfl_xor_sync(0xffffffffu, s0, 1);
                float r1 = __shfl_xor_sync(0xffffffffu, s1, 1);
                float zi, zf, zg, zo;
                if ((c & 1) == 0) { zi = A4[0]; zf = A4[1]; zg = r0; zo = r1; }
                else              { zi = r0;    zf = r1;    zg = A4[2]; zo = A4[3]; }
                // batched reciprocals: 5 exp + 2 rcp (args clamped; triple product stays finite)
                float ei = __expf(fminf(-zi, 25.0f));
                float ef = __expf(fminf(-zf, 25.0f));
                float ag = fabsf(zg);
                float eg = __expf(-2.0f * ag);
                float di = 1.0f + ei, df = 1.0f + ef, dg = 1.0f + eg;
                float rP = rcpf(di * df * dg);
                float sig_i = rP * (df * dg);
                float sig_f = rP * (di * dg);
                float th_g  = copysignf((1.0f - eg) * rP * (di * df), zg);
                float cn = sig_f * cst[s * 8 + j] + sig_i * th_g;
                cst[s * 8 + j] = cn;
                float eo = __expf(fminf(-zo, 25.0f));
                float ac = fabsf(cn);
                float ec = __expf(-2.0f * ac);
                float do_ = 1.0f + eo, dc = 1.0f + ec;
                float r2 = rcpf(do_ * dc);
                float hv = (r2 * dc) * copysignf((1.0f - ec) * r2 * do_, cn);
                int u = uO + 2 * j;
                px[s] = fmaf(hv, wout_f[u], px[s]);
                py[s] = fmaf(hv, wout_f[128 + u], py[s]);
                uint32_t hb = (uint32_t)__half_as_ushort(__float2half_rn(hv));
                if (j & 1) hpk[j >> 1] |= hb << 16; else hpk[j >> 1] = hb;
            }
            // write-back: k' = 16nc + 8dlt + j contiguous -> one STS.128 per row
            uint32_t ha = sb + A_OFF + (32 * mr + 16 * s + row_loc) * PITCH + (16 * nc + 8 * dlt) * 2;
            asm volatile("st.shared.v4.u32 [%0], {%1,%2,%3,%4};"
                         :: "r"(ha), "r"(hpk[0]), "r"(hpk[1]), "r"(hpk[2]), "r"(hpk[3]));
        }
#pragma unroll
        for (int s = 0; s < 2; s++) {
            px[s] += __shfl_xor_sync(0xffffffffu, px[s], 2);
            py[s] += __shfl_xor_sync(0xffffffffu, py[s], 2);
            if (c < 2)
                *(float2*)(relp_f + (nc * 64 + 32 * mr + 16 * s + row_loc) * 2) = make_float2(px[s], py[s]);
        }
        __syncthreads();
        if (tid < 128) {
            int m = tid >> 1, cp = tid & 1;
            float r = bout_f[cp];
#pragma unroll
            for (int k = 0; k < 8; k++) r += relp_f[(k * 64 + m) * 2 + cp];
            rels_f[m * 2 + cp] = r;
            out[(size_t)(b0 + m) * (T_STEPS * 2) + t * 2 + cp] = r;
        }
        __syncthreads();
        for (int i = tid; i < 1024; i += NT) {
            int m = i >> 4, e = i & 15;
            float xv = tanhf_(fmaf(wsp_f[2 * e], rels_f[m * 2],
                              fmaf(wsp_f[2 * e + 1], rels_f[m * 2 + 1], bsp_f[e])));
            unsigned short hv = __half_as_ushort(__float2half_rn(xv));
            asm volatile("st.shared.u16 [%0], %1;" :: "r"(sb + A_OFF + m * PITCH + (128 + e) * 2), "h"(hv));
        }
        // next iteration's first syncthreads orders these writes before A reads
    }
}

// ---------------- launch ----------------
extern "C" void kernel_launch(void* const* d_in, const int* in_sizes, int n_in,
                              void* d_out, int out_size) {
    const float* last_obs_rel = (const float*)d_in[1];
    const float* h0    = (const float*)d_in[2];
    const float* c0    = (const float*)d_in[3];
    const float* W_sp  = (const float*)d_in[4];
    const float* b_sp  = (const float*)d_in[5];
    const float* W_ih  = (const float*)d_in[6];
    const float* b_ih  = (const float*)d_in[7];
    const float* W_hh  = (const float*)d_in[8];
    const float* b_hh  = (const float*)d_in[9];
    const float* W_out = (const float*)d_in[10];
    const float* b_out = (const float*)d_in[11];
    float* out = (float*)d_out;

    const int batch = in_sizes[2] / 128;
    const int nblocks = batch / 64;

    cudaFuncSetAttribute(lstm_mma, cudaFuncAttributeMaxDynamicSharedMemorySize, SMEM_REQ);
    prep_kernel<<<146, 512>>>(W_ih, b_ih, W_hh, b_hh);
    lstm_mma<<<nblocks, NT, SMEM_REQ>>>(last_obs_rel, h0, c0, W_sp, b_sp, W_out, b_out, out);
}

// round 12
// speedup vs baseline: 2.6929x; 1.1632x over previous
#include <cuda_runtime.h>
#include <cuda_fp16.h>
#include <cstdint>

#define T_STEPS 30
#define NT 512
#define PITCH 336                 // A row pitch bytes (ldmatrix conflict-free)
#define NCHUNK9 (T_STEPS * 9)

// smem byte offsets
#define A_OFF    0                // 64 x 336 = 21504
#define RING_OFF 21504            // + g*65536 ; 2 slots x 32768 per group
#define BIAS_OFF 152576           // 512 f32
#define WOUT_OFF 154624           // 256 f32
#define WSP_OFF  155648           // 32 f32
#define BSP_OFF  155776           // 16 f32
#define BOUT_OFF 155840           // 2 f32
#define FLAG_OFF 155856           // skew flag
#define RELP_OFF 155872           // + g*2048 ; 8nc x 32row x 2 f32
#define RELS_OFF 159968           // + g*256  ; 32row x 2 f32
#define SMEM_REQ (160480 + 128)

// B image: 9 chunks x [ntg(64)][lane(32)][bh0,bh1,bl0,bl1]
__device__ uint32_t g_B[9 * 8192];
__device__ float    g_bias[512];   // indexed by n = 4u+g

__device__ __forceinline__ uint32_t smem_u32(const void* p) {
    uint32_t a;
    asm("{ .reg .u64 t; cvta.to.shared.u64 t, %1; cvt.u32.u64 %0, t; }" : "=r"(a) : "l"(p));
    return a;
}
__device__ __forceinline__ void mma16816(float* d, const uint32_t* a, uint32_t b0, uint32_t b1) {
    asm volatile("mma.sync.aligned.m16n8k16.row.col.f32.f16.f16.f32 "
                 "{%0,%1,%2,%3}, {%4,%5,%6,%7}, {%8,%9}, {%0,%1,%2,%3};"
                 : "+f"(d[0]), "+f"(d[1]), "+f"(d[2]), "+f"(d[3])
                 : "r"(a[0]), "r"(a[1]), "r"(a[2]), "r"(a[3]), "r"(b0), "r"(b1));
}
__device__ __forceinline__ void ldmatrix4(uint32_t* a, uint32_t addr) {
    asm volatile("ldmatrix.sync.aligned.m8n8.x4.shared.b16 {%0,%1,%2,%3}, [%4];"
                 : "=r"(a[0]), "=r"(a[1]), "=r"(a[2]), "=r"(a[3]) : "r"(addr));
}
__device__ __forceinline__ void lds_v4(uint32_t& x, uint32_t& y, uint32_t& z, uint32_t& u, uint32_t addr) {
    asm volatile("ld.shared.v4.u32 {%0,%1,%2,%3}, [%4];" : "=r"(x), "=r"(y), "=r"(z), "=r"(u) : "r"(addr));
}
__device__ __forceinline__ void cp16(uint32_t dst, const void* src) {
    asm volatile("cp.async.cg.shared.global [%0], [%1], 16;" :: "r"(dst), "l"(src) : "memory");
}
__device__ __forceinline__ void cp_commit() { asm volatile("cp.async.commit_group;" ::: "memory"); }
__device__ __forceinline__ float tanh_a(float x) {
    float r;
    asm("tanh.approx.f32 %0, %1;" : "=f"(r) : "f"(x));
    return r;
}
__device__ __forceinline__ float sig_a(float x) { return fmaf(tanh_a(0.5f * x), 0.5f, 0.5f); }
// k-permutation: unit u -> k' so each thread's owned units are k'-contiguous
__device__ __forceinline__ int sig_k(int u) {
    return 16 * (u >> 4) + 8 * (u & 1) + ((u & 15) >> 1);
}

// ---------------- prep: fragment-packed hi/lo fp16 B image + bias ----------------
__global__ void prep_kernel(const float* __restrict__ Wih, const float* __restrict__ bih,
                            const float* __restrict__ Whh, const float* __restrict__ bhh) {
    int idx = blockIdx.x * blockDim.x + threadIdx.x;
    if (idx < 73728) {
        int kt = idx / 8192, rem = idx - kt * 8192;
        int ntg = rem >> 7, r2 = rem & 127;
        int l = r2 >> 2, s = r2 & 3;
        int p = s >> 1, q = s & 1;
        int n = 8 * ntg + (l >> 2), c = l & 3;
        int row = (n & 3) * 128 + (n >> 2);
        uint32_t pk = 0;
#pragma unroll
        for (int h2 = 0; h2 < 2; h2++) {
            int k = 16 * kt + 2 * c + 8 * q + h2;
            float wv;
            if (k < 128) {
                int a2 = k >> 4, d2 = (k >> 3) & 1, b2 = k & 7;
                wv = Whh[row * 128 + (16 * a2 + 2 * b2 + d2)];
            } else {
                wv = Wih[row * 16 + (k - 128)];
            }
            __half hi = __float2half_rn(wv);
            __half v = p ? __float2half_rn(wv - __half2float(hi)) : hi;
            pk |= (uint32_t)__half_as_ushort(v) << (16 * h2);
        }
        g_B[idx] = pk;
    } else if (idx < 74240) {
        int n = idx - 73728;
        int row = (n & 3) * 128 + (n >> 2);
        g_bias[n] = bih[row] + bhh[row];
    }
}

// ---------------- main kernel ----------------
__global__ __launch_bounds__(NT, 1)
void lstm_mma(const float* __restrict__ rel_in, const float* __restrict__ h0,
              const float* __restrict__ c0, const float* __restrict__ W_sp,
              const float* __restrict__ b_sp, const float* __restrict__ W_out,
              const float* __restrict__ b_out, float* __restrict__ out) {
    extern __shared__ char sm_[];
    char* base = (char*)(((uintptr_t)sm_ + 127) & ~(uintptr_t)127);
    const uint32_t sb = smem_u32(base);
    const int tid = threadIdx.x, w = tid >> 5, l = tid & 31;
    const int g = w >> 3;                      // group 0/1: batch rows [32g, 32g+32)
    const int nc = w & 7;                      // n-cols [64nc, 64nc+64)
    const int tl = tid & 255;                  // thread index within group
    const int barid = 1 + g;
    const int c = l & 3, quad = l >> 2;
    const int dlt = c >> 1;
    const int row_loc = quad + 8 * (c & 1);    // local row within a 16-row tile
    const int b0 = blockIdx.x * 64;

    float* bias_f = (float*)(base + BIAS_OFF);
    float* wout_f = (float*)(base + WOUT_OFF);
    float* wsp_f  = (float*)(base + WSP_OFF);
    float* bsp_f  = (float*)(base + BSP_OFF);
    float* bout_f = (float*)(base + BOUT_OFF);
    float* relp_f = (float*)(base + RELP_OFF + g * 2048);
    float* rels_f = (float*)(base + RELS_OFF + g * 256);
    volatile int* flag = (volatile int*)(base + FLAG_OFF);

    if (tid < 512) bias_f[tid] = g_bias[tid];
    if (tid < 256) wout_f[tid] = W_out[tid];
    if (tid < 32)  wsp_f[tid]  = W_sp[tid];
    if (tid < 16)  bsp_f[tid]  = b_sp[tid];
    if (tid < 2)   bout_f[tid] = b_out[tid];
    if (tid == 0)  *flag = 0;

    // A init: h0 -> fp16 at permuted k' (all 64 rows, CTA-wide)
    for (int i = tid; i < 8192; i += NT) {
        int m = i >> 7, u = i & 127;
        unsigned short hv = __half_as_ushort(__float2half_rn(h0[(size_t)(b0 + m) * 128 + u]));
        asm volatile("st.shared.u16 [%0], %1;" :: "r"(sb + A_OFF + m * PITCH + sig_k(u) * 2), "h"(hv));
    }
    // x0 (uses global W_sp/b_sp)
    for (int i = tid; i < 1024; i += NT) {
        int m = i >> 4, e = i & 15;
        float r0 = rel_in[(size_t)(b0 + m) * 2], r1 = rel_in[(size_t)(b0 + m) * 2 + 1];
        float xv = tanh_a(fmaf(W_sp[2 * e], r0, fmaf(W_sp[2 * e + 1], r1, b_sp[e])));
        unsigned short hv = __half_as_ushort(__float2half_rn(xv));
        asm volatile("st.shared.u16 [%0], %1;" :: "r"(sb + A_OFF + m * PITCH + (128 + e) * 2), "h"(hv));
    }
    // c state: thread owns rows 32g+16s+row_loc (s=0,1), units 16nc+2j+dlt
    float cst[16];
#pragma unroll
    for (int s = 0; s < 2; s++)
#pragma unroll
        for (int j = 0; j < 8; j++)
            cst[s * 8 + j] = c0[(size_t)(b0 + 32 * g + 16 * s + row_loc) * 128 + (16 * nc + 2 * j + dlt)];

    // group-local 2-slot ring; prologue: stage chunks 0,1
    const uint32_t ring = sb + RING_OFF + g * 65536;
    {
        const char* s0 = (const char*)g_B;
#pragma unroll
        for (int r = 0; r < 8; r++) cp16(ring + (tl + r * 256) * 16, s0 + (tl + r * 256) * 16);
        cp_commit();
        const char* s1 = (const char*)(g_B + 8192);
#pragma unroll
        for (int r = 0; r < 8; r++) cp16(ring + 32768 + (tl + r * 256) * 16, s1 + (tl + r * 256) * 16);
        cp_commit();
    }
    __syncthreads();

    // initial anti-phase skew: group 1 waits until group 0 is mid-GEMM of t=0
    if (g == 1) { while (*flag == 0) __nanosleep(200); }

    const uint32_t aAddr0 = sb + A_OFF + (32 * g + (l & 15)) * PITCH + (l >> 4) * 16;
    const int uO = 16 * nc + dlt;

    for (int t = 0; t < T_STEPS; t++) {
        float acc[2][8][4];
#pragma unroll
        for (int j = 0; j < 8; j++) {
            float2 bv = *(const float2*)(bias_f + (8 * (nc * 8 + j) + 2 * c));
#pragma unroll
            for (int s = 0; s < 2; s++) {
                acc[s][j][0] = bv.x; acc[s][j][1] = bv.y;
                acc[s][j][2] = bv.x; acc[s][j][3] = bv.y;
            }
        }
#pragma unroll 1
        for (int kt = 0; kt < 9; kt++) {
            int q = t * 9 + kt;
            asm volatile("cp.async.wait_group 1;" ::: "memory");
            asm volatile("bar.sync %0, 256;" :: "r"(barid) : "memory");
            uint32_t a0[4], a1[4];
            ldmatrix4(a0, aAddr0 + kt * 32);
            ldmatrix4(a1, aAddr0 + 16 * PITCH + kt * 32);
            uint32_t baddr = ring + (q & 1) * 32768 + ((nc * 8) * 32 + l) * 16;
#pragma unroll
            for (int j = 0; j < 8; j++) {
                uint32_t bh0, bh1, bl0, bl1;
                lds_v4(bh0, bh1, bl0, bl1, baddr);
                mma16816(acc[0][j], a0, bh0, bh1);
                mma16816(acc[0][j], a0, bl0, bl1);
                mma16816(acc[1][j], a1, bh0, bh1);
                mma16816(acc[1][j], a1, bl0, bl1);
                baddr += 512;
            }
            asm volatile("bar.sync %0, 256;" :: "r"(barid) : "memory");
            if (g == 0 && t == 0 && kt == 4 && tid == 0) *flag = 1;
            if (q + 2 < NCHUNK9) {
                const char* src = (const char*)(g_B + ((q + 2) % 9) * 8192);
                uint32_t dst = ring + (q & 1) * 32768;
#pragma unroll
                for (int r = 0; r < 8; r++) cp16(dst + (tl + r * 256) * 16, src + (tl + r * 256) * 16);
                cp_commit();
            }
        }

        // ---- epilogue (tanh.approx activations) ----
        float px[2] = {0.f, 0.f}, py[2] = {0.f, 0.f};
#pragma unroll
        for (int s = 0; s < 2; s++) {
            uint32_t hpk[4];
#pragma unroll
            for (int j = 0; j < 8; j++) {
                float* A4 = acc[s][j];
                float s0 = (c & 1) ? A4[0] : A4[2];
                float s1 = (c & 1) ? A4[1] : A4[3];
                float r0 = __shfl_xor_sync(0xffffffffu, s0, 1);
                float r1 = __shfl_xor_sync(0xffffffffu, s1, 1);
                float zi, zf, zg, zo;
                if ((c & 1) == 0) { zi = A4[0]; zf = A4[1]; zg = r0; zo = r1; }
                else              { zi = r0;    zf = r1;    zg = A4[2]; zo = A4[3]; }
                float cn = sig_a(zf) * cst[s * 8 + j] + sig_a(zi) * tanh_a(zg);
                cst[s * 8 + j] = cn;
                float hv = sig_a(zo) * tanh_a(cn);
                int u = uO + 2 * j;
                px[s] = fmaf(hv, wout_f[u], px[s]);
                py[s] = fmaf(hv, wout_f[128 + u], py[s]);
                uint32_t hb = (uint32_t)__half_as_ushort(__float2half_rn(hv));
                if (j & 1) hpk[j >> 1] |= hb << 16; else hpk[j >> 1] = hb;
            }
            uint32_t ha = sb + A_OFF + (32 * g + 16 * s + row_loc) * PITCH + (16 * nc + 8 * dlt) * 2;
            asm volatile("st.shared.v4.u32 [%0], {%1,%2,%3,%4};"
                         :: "r"(ha), "r"(hpk[0]), "r"(hpk[1]), "r"(hpk[2]), "r"(hpk[3]));
        }
#pragma unroll
        for (int s = 0; s < 2; s++) {
            px[s] += __shfl_xor_sync(0xffffffffu, px[s], 2);
            py[s] += __shfl_xor_sync(0xffffffffu, py[s], 2);
            if (c < 2)
                *(float2*)(relp_f + (nc * 32 + 16 * s + row_loc) * 2) = make_float2(px[s], py[s]);
        }
        asm volatile("bar.sync %0, 256;" :: "r"(barid) : "memory");
        if (tl < 64) {
            int mloc = tl >> 1, cp = tl & 1;
            float r = bout_f[cp];
#pragma unroll
            for (int k = 0; k < 8; k++) r += relp_f[(k * 32 + mloc) * 2 + cp];
            rels_f[mloc * 2 + cp] = r;
            out[(size_t)(b0 + 32 * g + mloc) * (T_STEPS * 2) + t * 2 + cp] = r;
        }
        asm volatile("bar.sync %0, 256;" :: "r"(barid) : "memory");
        // x update (group's own 32 rows)
        for (int i = tl; i < 512; i += 256) {
            int mloc = i >> 4, e = i & 15;
            float xv = tanh_a(fmaf(wsp_f[2 * e], rels_f[mloc * 2],
                              fmaf(wsp_f[2 * e + 1], rels_f[mloc * 2 + 1], bsp_f[e])));
            unsigned short hv = __half_as_ushort(__float2half_rn(xv));
            asm volatile("st.shared.u16 [%0], %1;"
                         :: "r"(sb + A_OFF + (32 * g + mloc) * PITCH + (128 + e) * 2), "h"(hv));
        }
        // next step's first group barrier orders these writes before A reads
    }
}

// ---------------- launch ----------------
extern "C" void kernel_launch(void* const* d_in, const int* in_sizes, int n_in,
                              void* d_out, int out_size) {
    const float* last_obs_rel = (const float*)d_in[1];
    const float* h0    = (const float*)d_in[2];
    const float* c0    = (const float*)d_in[3];
    const float* W_sp  = (const float*)d_in[4];
    const float* b_sp  = (const float*)d_in[5];
    const float* W_ih  = (const float*)d_in[6];
    const float* b_ih  = (const float*)d_in[7];
    const float* W_hh  = (const float*)d_in[8];
    const float* b_hh  = (const float*)d_in[9];
    const float* W_out = (const float*)d_in[10];
    const float* b_out = (const float*)d_in[11];
    float* out = (float*)d_out;

    const int batch = in_sizes[2] / 128;
    const int nblocks = batch / 64;

    cudaFuncSetAttribute(lstm_mma, cudaFuncAttributeMaxDynamicSharedMemorySize, SMEM_REQ);
    prep_kernel<<<146, 512>>>(W_ih, b_ih, W_hh, b_hh);
    lstm_mma<<<nblocks, NT, SMEM_REQ>>>(last_obs_rel, h0, c0, W_sp, b_sp, W_out, b_out, out);
}

// round 13
// speedup vs baseline: 3.3798x; 1.2551x over previous
#include <cuda_runtime.h>
#include <cuda_fp16.h>
#include <cstdint>

#define T_STEPS 30
#define NT 512
#define PITCH 336                 // A row pitch bytes (ldmatrix conflict-free)

// smem byte offsets
#define A_OFF    0                // 64 x 336 = 21504
#define BIAS_OFF 21504            // 512 f32
#define WOUT_OFF 23552            // 256 f32
#define WSP_OFF  24576            // 32 f32
#define BSP_OFF  24704            // 16 f32
#define BOUT_OFF 24768            // 2 f32
#define FLAG_OFF 24784            // skew flag
#define RELP_OFF 24800            // + g*2048 ; 8nc x 32row x 2 f32
#define RELS_OFF 28896            // + g*256  ; 32row x 2 f32
#define SMEM_REQ (29408 + 128)

// B image: 9 chunks x [ntg(64)][lane(32)][bh0,bh1,bl0,bl1] (fragment-packed, L2-resident)
__device__ uint32_t g_B[9 * 8192];
__device__ float    g_bias[512];   // indexed by n = 4u+g

__device__ __forceinline__ uint32_t smem_u32(const void* p) {
    uint32_t a;
    asm("{ .reg .u64 t; cvta.to.shared.u64 t, %1; cvt.u32.u64 %0, t; }" : "=r"(a) : "l"(p));
    return a;
}
__device__ __forceinline__ void mma16816(float* d, const uint32_t* a, uint32_t b0, uint32_t b1) {
    asm volatile("mma.sync.aligned.m16n8k16.row.col.f32.f16.f16.f32 "
                 "{%0,%1,%2,%3}, {%4,%5,%6,%7}, {%8,%9}, {%0,%1,%2,%3};"
                 : "+f"(d[0]), "+f"(d[1]), "+f"(d[2]), "+f"(d[3])
                 : "r"(a[0]), "r"(a[1]), "r"(a[2]), "r"(a[3]), "r"(b0), "r"(b1));
}
__device__ __forceinline__ void ldmatrix4(uint32_t* a, uint32_t addr) {
    asm volatile("ldmatrix.sync.aligned.m8n8.x4.shared.b16 {%0,%1,%2,%3}, [%4];"
                 : "=r"(a[0]), "=r"(a[1]), "=r"(a[2]), "=r"(a[3]) : "r"(addr));
}
__device__ __forceinline__ float tanh_a(float x) {
    float r;
    asm("tanh.approx.f32 %0, %1;" : "=f"(r) : "f"(x));
    return r;
}
__device__ __forceinline__ float sig_a(float x) { return fmaf(tanh_a(0.5f * x), 0.5f, 0.5f); }
// k-permutation: unit u -> k' so each thread's owned units are k'-contiguous
__device__ __forceinline__ int sig_k(int u) {
    return 16 * (u >> 4) + 8 * (u & 1) + ((u & 15) >> 1);
}

// ---------------- prep: fragment-packed hi/lo fp16 B image + bias ----------------
__global__ void prep_kernel(const float* __restrict__ Wih, const float* __restrict__ bih,
                            const float* __restrict__ Whh, const float* __restrict__ bhh) {
    int idx = blockIdx.x * blockDim.x + threadIdx.x;
    if (idx < 73728) {
        int kt = idx / 8192, rem = idx - kt * 8192;
        int ntg = rem >> 7, r2 = rem & 127;
        int l = r2 >> 2, s = r2 & 3;
        int p = s >> 1, q = s & 1;
        int n = 8 * ntg + (l >> 2), c = l & 3;
        int row = (n & 3) * 128 + (n >> 2);
        uint32_t pk = 0;
#pragma unroll
        for (int h2 = 0; h2 < 2; h2++) {
            int k = 16 * kt + 2 * c + 8 * q + h2;
            float wv;
            if (k < 128) {
                int a2 = k >> 4, d2 = (k >> 3) & 1, b2 = k & 7;
                wv = Whh[row * 128 + (16 * a2 + 2 * b2 + d2)];
            } else {
                wv = Wih[row * 16 + (k - 128)];
            }
            __half hi = __float2half_rn(wv);
            __half v = p ? __float2half_rn(wv - __half2float(hi)) : hi;
            pk |= (uint32_t)__half_as_ushort(v) << (16 * h2);
        }
        g_B[idx] = pk;
    } else if (idx < 74240) {
        int n = idx - 73728;
        int row = (n & 3) * 128 + (n >> 2);
        g_bias[n] = bih[row] + bhh[row];
    }
}

// ---------------- main kernel ----------------
__global__ __launch_bounds__(NT, 1)
void lstm_mma(const float* __restrict__ rel_in, const float* __restrict__ h0,
              const float* __restrict__ c0, const float* __restrict__ W_sp,
              const float* __restrict__ b_sp, const float* __restrict__ W_out,
              const float* __restrict__ b_out, float* __restrict__ out) {
    extern __shared__ char sm_[];
    char* base = (char*)(((uintptr_t)sm_ + 127) & ~(uintptr_t)127);
    const uint32_t sb = smem_u32(base);
    const int tid = threadIdx.x, w = tid >> 5, l = tid & 31;
    const int g = w >> 3;                      // group 0/1: batch rows [32g, 32g+32)
    const int nc = w & 7;                      // n-cols [64nc, 64nc+64)
    const int tl = tid & 255;
    const int barid = 1 + g;
    const int c = l & 3, quad = l >> 2;
    const int dlt = c >> 1;
    const int row_loc = quad + 8 * (c & 1);
    const int b0 = blockIdx.x * 64;

    float* bias_f = (float*)(base + BIAS_OFF);
    float* wout_f = (float*)(base + WOUT_OFF);
    float* wsp_f  = (float*)(base + WSP_OFF);
    float* bsp_f  = (float*)(base + BSP_OFF);
    float* bout_f = (float*)(base + BOUT_OFF);
    float* relp_f = (float*)(base + RELP_OFF + g * 2048);
    float* rels_f = (float*)(base + RELS_OFF + g * 256);
    volatile int* flag = (volatile int*)(base + FLAG_OFF);

    if (tid < 512) bias_f[tid] = g_bias[tid];
    if (tid < 256) wout_f[tid] = W_out[tid];
    if (tid < 32)  wsp_f[tid]  = W_sp[tid];
    if (tid < 16)  bsp_f[tid]  = b_sp[tid];
    if (tid < 2)   bout_f[tid] = b_out[tid];
    if (tid == 0)  *flag = 0;

    // A init: h0 -> fp16 at permuted k'
    for (int i = tid; i < 8192; i += NT) {
        int m = i >> 7, u = i & 127;
        unsigned short hv = __half_as_ushort(__float2half_rn(h0[(size_t)(b0 + m) * 128 + u]));
        asm volatile("st.shared.u16 [%0], %1;" :: "r"(sb + A_OFF + m * PITCH + sig_k(u) * 2), "h"(hv));
    }
    // x0
    for (int i = tid; i < 1024; i += NT) {
        int m = i >> 4, e = i & 15;
        float r0 = rel_in[(size_t)(b0 + m) * 2], r1 = rel_in[(size_t)(b0 + m) * 2 + 1];
        float xv = tanh_a(fmaf(W_sp[2 * e], r0, fmaf(W_sp[2 * e + 1], r1, b_sp[e])));
        unsigned short hv = __half_as_ushort(__float2half_rn(xv));
        asm volatile("st.shared.u16 [%0], %1;" :: "r"(sb + A_OFF + m * PITCH + (128 + e) * 2), "h"(hv));
    }
    // c state
    float cst[16];
#pragma unroll
    for (int s = 0; s < 2; s++)
#pragma unroll
        for (int j = 0; j < 8; j++)
            cst[s * 8 + j] = c0[(size_t)(b0 + 32 * g + 16 * s + row_loc) * 128 + (16 * nc + 2 * j + dlt)];

    __syncthreads();

    // initial anti-phase skew: group 1 starts half a GEMM later
    if (g == 1) { while (*flag == 0) __nanosleep(200); }

    const uint32_t aAddr0 = sb + A_OFF + (32 * g + (l & 15)) * PITCH + (l >> 4) * 16;
    const int uO = 16 * nc + dlt;
    const uint4* __restrict__ bbase = ((const uint4*)g_B) + (nc * 256 + l);  // +kt*2048 +j*32

    for (int t = 0; t < T_STEPS; t++) {
        float acc[2][8][4];
#pragma unroll
        for (int j = 0; j < 8; j++) {
            float2 bv = *(const float2*)(bias_f + (8 * (nc * 8 + j) + 2 * c));
#pragma unroll
            for (int s = 0; s < 2; s++) {
                acc[s][j][0] = bv.x; acc[s][j][1] = bv.y;
                acc[s][j][2] = bv.x; acc[s][j][3] = bv.y;
            }
        }
        asm volatile("bar.sync %0, 256;" :: "r"(barid) : "memory");  // h/x writes visible

        // ---- free-running GEMM: 72-stage pipeline, no barriers ----
        uint32_t aq[2][2][4];
        ldmatrix4(aq[0][0], aAddr0);
        ldmatrix4(aq[0][1], aAddr0 + 16 * PITCH);
        uint4 bb[3];
        bb[0] = bbase[0];
        bb[1] = bbase[32];
#pragma unroll
        for (int i = 0; i < 72; i++) {
            const int kt = i >> 3, j = i & 7;
            if (i + 2 < 72) {
                const int i2 = i + 2;
                bb[i2 % 3] = bbase[(i2 >> 3) * 2048 + (i2 & 7) * 32];
            }
            if (j == 6 && kt < 8) {
                ldmatrix4(aq[(kt + 1) & 1][0], aAddr0 + (kt + 1) * 32);
                ldmatrix4(aq[(kt + 1) & 1][1], aAddr0 + 16 * PITCH + (kt + 1) * 32);
            }
            const uint4 b = bb[i % 3];
            uint32_t* a0 = aq[kt & 1][0];
            uint32_t* a1 = aq[kt & 1][1];
            mma16816(acc[0][j], a0, b.x, b.y);
            mma16816(acc[0][j], a0, b.z, b.w);
            mma16816(acc[1][j], a1, b.x, b.y);
            mma16816(acc[1][j], a1, b.z, b.w);
            if (i == 36 && t == 0 && g == 0 && tid == 0) *flag = 1;
        }
        asm volatile("bar.sync %0, 256;" :: "r"(barid) : "memory");  // A reads done

        // ---- epilogue ----
        float px[2] = {0.f, 0.f}, py[2] = {0.f, 0.f};
#pragma unroll
        for (int s = 0; s < 2; s++) {
            uint32_t hpk[4];
#pragma unroll
            for (int j = 0; j < 8; j++) {
                float* A4 = acc[s][j];
                float s0 = (c & 1) ? A4[0] : A4[2];
                float s1 = (c & 1) ? A4[1] : A4[3];
                float r0 = __shfl_xor_sync(0xffffffffu, s0, 1);
                float r1 = __shfl_xor_sync(0xffffffffu, s1, 1);
                float zi, zf, zg, zo;
                if ((c & 1) == 0) { zi = A4[0]; zf = A4[1]; zg = r0; zo = r1; }
                else              { zi = r0;    zf = r1;    zg = A4[2]; zo = A4[3]; }
                float cn = sig_a(zf) * cst[s * 8 + j] + sig_a(zi) * tanh_a(zg);
                cst[s * 8 + j] = cn;
                float hv = sig_a(zo) * tanh_a(cn);
                int u = uO + 2 * j;
                px[s] = fmaf(hv, wout_f[u], px[s]);
                py[s] = fmaf(hv, wout_f[128 + u], py[s]);
                uint32_t hb = (uint32_t)__half_as_ushort(__float2half_rn(hv));
                if (j & 1) hpk[j >> 1] |= hb << 16; else hpk[j >> 1] = hb;
            }
            uint32_t ha = sb + A_OFF + (32 * g + 16 * s + row_loc) * PITCH + (16 * nc + 8 * dlt) * 2;
            asm volatile("st.shared.v4.u32 [%0], {%1,%2,%3,%4};"
                         :: "r"(ha), "r"(hpk[0]), "r"(hpk[1]), "r"(hpk[2]), "r"(hpk[3]));
        }
#pragma unroll
        for (int s = 0; s < 2; s++) {
            px[s] += __shfl_xor_sync(0xffffffffu, px[s], 2);
            py[s] += __shfl_xor_sync(0xffffffffu, py[s], 2);
            if (c < 2)
                *(float2*)(relp_f + (nc * 32 + 16 * s + row_loc) * 2) = make_float2(px[s], py[s]);
        }
        asm volatile("bar.sync %0, 256;" :: "r"(barid) : "memory");  // relp visible
        if (tl < 64) {
            int mloc = tl >> 1, cp = tl & 1;
            float r = bout_f[cp];
#pragma unroll
            for (int k = 0; k < 8; k++) r += relp_f[(k * 32 + mloc) * 2 + cp];
            rels_f[mloc * 2 + cp] = r;
            out[(size_t)(b0 + 32 * g + mloc) * (T_STEPS * 2) + t * 2 + cp] = r;
        }
        asm volatile("bar.sync %0, 256;" :: "r"(barid) : "memory");  // rels visible
        for (int i = tl; i < 512; i += 256) {
            int mloc = i >> 4, e = i & 15;
            float xv = tanh_a(fmaf(wsp_f[2 * e], rels_f[mloc * 2],
                              fmaf(wsp_f[2 * e + 1], rels_f[mloc * 2 + 1], bsp_f[e])));
            unsigned short hv = __half_as_ushort(__float2half_rn(xv));
            asm volatile("st.shared.u16 [%0], %1;"
                         :: "r"(sb + A_OFF + (32 * g + mloc) * PITCH + (128 + e) * 2), "h"(hv));
        }
        // next step's first group barrier orders these writes before A reads
    }
}

// ---------------- launch ----------------
extern "C" void kernel_launch(void* const* d_in, const int* in_sizes, int n_in,
                              void* d_out, int out_size) {
    const float* last_obs_rel = (const float*)d_in[1];
    const float* h0    = (const float*)d_in[2];
    const float* c0    = (const float*)d_in[3];
    const float* W_sp  = (const float*)d_in[4];
    const float* b_sp  = (const float*)d_in[5];
    const float* W_ih  = (const float*)d_in[6];
    const float* b_ih  = (const float*)d_in[7];
    const float* W_hh  = (const float*)d_in[8];
    const float* b_hh  = (const float*)d_in[9];
    const float* W_out = (const float*)d_in[10];
    const float* b_out = (const float*)d_in[11];
    float* out = (float*)d_out;

    const int batch = in_sizes[2] / 128;
    const int nblocks = batch / 64;

    cudaFuncSetAttribute(lstm_mma, cudaFuncAttributeMaxDynamicSharedMemorySize, SMEM_REQ);
    prep_kernel<<<146, 512>>>(W_ih, b_ih, W_hh, b_hh);
    lstm_mma<<<nblocks, NT, SMEM_REQ>>>(last_obs_rel, h0, c0, W_sp, b_sp, W_out, b_out, out);
}